// round 9
// baseline (speedup 1.0000x reference)
#include <cuda_runtime.h>
#include <cuda_fp16.h>
#include <cstdint>

// Batch Conv1D, implicit-im2col GEMM on mma.sync.
// Round 9: f16-ACCUMULATOR HMMA (theory: f32-acc HMMA is half-rate on sm_103's
// legacy pipe — R3/R5 both pin at 512 MAC/cyc/SM; f16-acc should be 1024).
// f16 partials accumulate over k=64 windows, then promote to persistent fp32
// accumulators (error budget ~4e-4 << 1e-3). R3 skeleton: 8 warps, 32x64 warp
// tiles, 4-stage cp.async ring. x/W pre-converted to fp16.

namespace {

constexpr int LOUT = 1022;
constexpr int NIT  = 24;                  // 768 k / 32
constexpr int NTHREADS = 256;
constexpr int STAGES = 4;

constexpr int A_STRIDE = 80;              // 32 fp16 (64B) + 16B pad
constexpr int A_BYTES  = 128 * A_STRIDE;  // 10240
constexpr int B_STRIDE = 272;             // 128 fp16 (256B) + 16B pad
constexpr int B_BYTES  = 32 * B_STRIDE;   // 8704

constexpr int OFF_A = 0;
constexpr int OFF_B = STAGES * A_BYTES;               // 40960
constexpr int SMEM_TOTAL = OFF_B + STAGES * B_BYTES;  // 75776

constexpr size_t X_ELEMS = 256u * 1024u * 256u;

__device__ __half g_wf16[768 * 256];
__device__ __half g_xh[X_ELEMS + 1024];   // +pad: rows 1022/1023 im2col overrun

// ---------------- PTX helpers ----------------

__device__ __forceinline__ uint32_t smem_u32(const void* p) {
    return (uint32_t)__cvta_generic_to_shared(p);
}
__device__ __forceinline__ void cp16(uint32_t dst, const void* src) {
    asm volatile("cp.async.cg.shared.global [%0], [%1], 16;" :: "r"(dst), "l"(src));
}
__device__ __forceinline__ void cp_commit() {
    asm volatile("cp.async.commit_group;" ::: "memory");
}
__device__ __forceinline__ void cp_wait2() {
    asm volatile("cp.async.wait_group 2;" ::: "memory");
}
__device__ __forceinline__ void ldsm4(uint32_t (&r)[4], uint32_t addr) {
    asm volatile("ldmatrix.sync.aligned.m8n8.x4.shared.b16 {%0,%1,%2,%3}, [%4];"
                 : "=r"(r[0]), "=r"(r[1]), "=r"(r[2]), "=r"(r[3]) : "r"(addr));
}
__device__ __forceinline__ void ldsm4t(uint32_t (&r)[4], uint32_t addr) {
    asm volatile("ldmatrix.sync.aligned.m8n8.x4.trans.shared.b16 {%0,%1,%2,%3}, [%4];"
                 : "=r"(r[0]), "=r"(r[1]), "=r"(r[2]), "=r"(r[3]) : "r"(addr));
}
// f16-accumulator HMMA: d,c are 2x b32 regs (4 halves)
__device__ __forceinline__ void mma16816_h(uint32_t (&d)[2], const uint32_t (&a)[4],
                                           uint32_t b0, uint32_t b1) {
    asm volatile(
        "mma.sync.aligned.m16n8k16.row.col.f16.f16.f16.f16 "
        "{%0,%1}, {%2,%3,%4,%5}, {%6,%7}, {%0,%1};"
        : "+r"(d[0]), "+r"(d[1])
        : "r"(a[0]), "r"(a[1]), "r"(a[2]), "r"(a[3]), "r"(b0), "r"(b1));
}

// ---------------- pre-passes ----------------

__global__ void xconv_kernel(const float* __restrict__ x) {
    size_t i = (size_t)blockIdx.x * 256 + threadIdx.x;
    const float4 v0 = *(const float4*)(x + i * 8);
    const float4 v1 = *(const float4*)(x + i * 8 + 4);
    __half2 h0 = __floats2half2_rn(v0.x, v0.y);
    __half2 h1 = __floats2half2_rn(v0.z, v0.w);
    __half2 h2 = __floats2half2_rn(v1.x, v1.y);
    __half2 h3 = __floats2half2_rn(v1.z, v1.w);
    uint4 p;
    p.x = *(uint32_t*)&h0; p.y = *(uint32_t*)&h1;
    p.z = *(uint32_t*)&h2; p.w = *(uint32_t*)&h3;
    *(uint4*)(g_xh + i * 8) = p;
}

__global__ void wconv_kernel(const float* __restrict__ W) {
    int i = blockIdx.x * 256 + threadIdx.x;
    g_wf16[i] = __float2half_rn(W[i]);
}

// ---------------- main GEMM ----------------

__global__ __launch_bounds__(NTHREADS, 1)
void conv1d_hmma_kernel(const float* __restrict__ bias, float* __restrict__ out)
{
    extern __shared__ __align__(128) uint8_t smem[];
    const uint32_t sm = smem_u32(smem);

    const int tid  = threadIdx.x;
    const int wid  = tid >> 5;
    const int lane = tid & 31;

    const int f0  = blockIdx.x * 128;
    const int l0  = blockIdx.y * 128;
    const int img = blockIdx.z;

    const __half* xb = g_xh + (size_t)img * (1024 * 256);
    float*        ob = out  + (size_t)img * (LOUT * 256);

    // 4x2 warp grid, 32x64 warp tiles (R3 layout)
    const int wm = (wid >> 1) * 32;
    const int wn = (wid & 1) * 64;

    // ldmatrix lane bases
    const uint32_t a_lane = (uint32_t)(wm + (lane & 15)) * A_STRIDE + (lane >> 4) * 16;
    const uint32_t b_lane = (uint32_t)(lane & 15) * B_STRIDE
                          + (uint32_t)(wn + (lane >> 4) * 8) * 2;

    // staging mappings (R3-proven)
    const int a_row = tid >> 1;
    const int a_sg  = tid & 1;
    const __half* a_src = xb + (size_t)(l0 + a_row) * 256 + a_sg * 16;
    const uint32_t a_dst = (uint32_t)a_row * A_STRIDE + a_sg * 32;

    const int b_row = tid >> 3;
    const int b_cg  = tid & 7;
    const __half* b_src = g_wf16 + (size_t)b_row * 256 + f0 + b_cg * 16;
    const uint32_t b_dst = (uint32_t)b_row * B_STRIDE + b_cg * 32;

    auto stage = [&](int t) {
        const int buf = t & (STAGES - 1);
        const __half* as = a_src + t * 32;
        const uint32_t ad = sm + OFF_A + buf * A_BYTES + a_dst;
        cp16(ad,      as);
        cp16(ad + 16, as + 8);
        const __half* bs = b_src + (size_t)t * 32 * 256;
        const uint32_t bd = sm + OFF_B + buf * B_BYTES + b_dst;
        cp16(bd,      bs);
        cp16(bd + 16, bs + 8);
        cp_commit();
    };

    // persistent fp32 accumulators + windowed f16 accumulators
    float acc[2][8][4];
    #pragma unroll
    for (int mt = 0; mt < 2; ++mt)
        #pragma unroll
        for (int nt = 0; nt < 8; ++nt)
            #pragma unroll
            for (int q = 0; q < 4; ++q)
                acc[mt][nt][q] = 0.f;

    uint32_t hacc[2][8][2];
    #pragma unroll
    for (int mt = 0; mt < 2; ++mt)
        #pragma unroll
        for (int nt = 0; nt < 8; ++nt) {
            hacc[mt][nt][0] = 0u;
            hacc[mt][nt][1] = 0u;
        }

    // prologue: fill 3 stages
    stage(0);
    stage(1);
    stage(2);

    for (int t = 0; t < NIT; ++t) {
        cp_wait2();                 // stage t landed
        __syncthreads();            // + everyone done reading buf (t+3)&3

        if (t + 3 < NIT) stage(t + 3);

        const uint32_t sA = sm + OFF_A + (t & (STAGES - 1)) * A_BYTES;
        const uint32_t sB = sm + OFF_B + (t & (STAGES - 1)) * B_BYTES;

        #pragma unroll
        for (int ks = 0; ks < 2; ++ks) {
            uint32_t af[2][4];
            ldsm4(af[0], sA + a_lane + ks * 32);
            ldsm4(af[1], sA + a_lane + 16 * A_STRIDE + ks * 32);
            uint32_t bf[4][4];
            #pragma unroll
            for (int n2 = 0; n2 < 4; ++n2)
                ldsm4t(bf[n2], sB + b_lane + ks * (16 * B_STRIDE) + n2 * 32);
            #pragma unroll
            for (int mt = 0; mt < 2; ++mt)
                #pragma unroll
                for (int n2 = 0; n2 < 4; ++n2) {
                    mma16816_h(hacc[mt][2 * n2],     af[mt], bf[n2][0], bf[n2][1]);
                    mma16816_h(hacc[mt][2 * n2 + 1], af[mt], bf[n2][2], bf[n2][3]);
                }
        }

        // promote f16 window -> fp32 every 2 steps (k=64 window)
        if ((t & 1) == 1) {
            #pragma unroll
            for (int mt = 0; mt < 2; ++mt)
                #pragma unroll
                for (int nt = 0; nt < 8; ++nt) {
                    float2 p0 = __half22float2(*reinterpret_cast<__half2*>(&hacc[mt][nt][0]));
                    float2 p1 = __half22float2(*reinterpret_cast<__half2*>(&hacc[mt][nt][1]));
                    acc[mt][nt][0] += p0.x;
                    acc[mt][nt][1] += p0.y;
                    acc[mt][nt][2] += p1.x;
                    acc[mt][nt][3] += p1.y;
                    hacc[mt][nt][0] = 0u;
                    hacc[mt][nt][1] = 0u;
                }
        }
    }

    // ---- epilogue: bias + guarded store from fp32 registers ----
    const int g  = lane >> 2;
    const int tq = lane & 3;
    #pragma unroll
    for (int nt = 0; nt < 8; ++nt) {
        const int col = f0 + wn + nt * 8 + tq * 2;
        const float b0 = __ldg(bias + col);
        const float b1 = __ldg(bias + col + 1);
        #pragma unroll
        for (int mt = 0; mt < 2; ++mt) {
            const int r = l0 + wm + mt * 16 + g;
            if (r < LOUT) {
                float2 v = make_float2(acc[mt][nt][0] + b0, acc[mt][nt][1] + b1);
                *(float2*)(ob + (size_t)r * 256 + col) = v;
            }
            if (r + 8 < LOUT) {
                float2 v = make_float2(acc[mt][nt][2] + b0, acc[mt][nt][3] + b1);
                *(float2*)(ob + (size_t)(r + 8) * 256 + col) = v;
            }
        }
    }
}

}  // namespace

extern "C" void kernel_launch(void* const* d_in, const int* in_sizes, int n_in,
                              void* d_out, int out_size)
{
    const float* x  = (const float*)d_in[0];   // [8,32,1024,256]
    const float* w  = (const float*)d_in[1];   // [3,256,256]
    const float* b  = (const float*)d_in[2];   // [256]
    float* out      = (float*)d_out;           // [8,32,1022,256]

    xconv_kernel<<<(int)(X_ELEMS / 8 / 256), 256>>>(x);  // x fp32 -> fp16
    wconv_kernel<<<768, 256>>>(w);                       // W fp32 -> fp16

    cudaFuncSetAttribute(conv1d_hmma_kernel,
                         cudaFuncAttributeMaxDynamicSharedMemorySize, SMEM_TOTAL);

    dim3 grid(2, 8, 256);                      // f-tiles, m-tiles, images
    conv1d_hmma_kernel<<<grid, NTHREADS, SMEM_TOTAL>>>(b, out);
}

// round 10
// speedup vs baseline: 1.0124x; 1.0124x over previous
#include <cuda_runtime.h>
#include <cuda_fp16.h>
#include <cstdint>

// Batch Conv1D via 1D Winograd F(2,3) on mma.sync (HMMA fp16 in / fp32 acc).
// Legacy mma.sync is capped at 512 MAC/cyc/SM on sm_103 (measured across 7
// kernels); R3's 357us GEMM is at 100% of that pipe. Winograd cuts MACs 1.5x:
//   z0=d0-d2, z1=d1+d2, z2=d2-d1, z3=d1-d3   (d_i = x[2t+i], per channel)
//   w0=g0, w1=(g0+g1+g2)/2, w2=(g0-g1+g2)/2, w3=g2
//   m_p = sum_c z_p*w_p ;  y[2t]=m0+m1+m2, y[2t+1]=m1-m2-m3
// CTA: 64 tile-pairs x 128 feats, all 4 phases. Warps 0-3: phases {0,1},
// warps 4-7: phases {2,3} (same 2x2 spatial grid); epilogue combines via smem.
// Input transform fused into staging (x fp32 cp.async -> smem transform).

namespace {

constexpr int NTILES = 511;               // output pairs per image (2*511=1022)
constexpr int NCHUNK = 8;                 // 256 channels / 32
constexpr int NTHREADS = 256;

constexpr int X_STRIDE = 144;             // 32 fp32 (128B) + 16B pad
constexpr int SLOT_X   = 18816;           // 130 rows * 144 = 18720, padded
constexpr int B_STRIDE = 272;             // 128 fp16 (256B) + 16B pad
constexpr int B_PHASE  = 32 * B_STRIDE;   // 8704
constexpr int SLOT_B   = 4 * B_PHASE;     // 34816
constexpr int SLOT     = SLOT_X + SLOT_B; // 53632
constexpr int OFF_Z    = 3 * SLOT;        // 160896
constexpr int Z_STRIDE = 80;              // 32 fp16 + pad
constexpr int Z_PHASE  = 64 * Z_STRIDE;   // 5120
constexpr int Z_BUF    = 4 * Z_PHASE;     // 20480
constexpr int SMEM_TOTAL = OFF_Z + 2 * Z_BUF;   // 201856

__device__ __half g_wt[4 * 256 * 256];    // [phase][c][f] Winograd weights

// ---------------- PTX helpers ----------------

__device__ __forceinline__ uint32_t smem_u32(const void* p) {
    return (uint32_t)__cvta_generic_to_shared(p);
}
__device__ __forceinline__ void cp16(uint32_t dst, const void* src) {
    asm volatile("cp.async.cg.shared.global [%0], [%1], 16;" :: "r"(dst), "l"(src));
}
__device__ __forceinline__ void cp_commit() {
    asm volatile("cp.async.commit_group;" ::: "memory");
}
__device__ __forceinline__ void cp_wait1() {
    asm volatile("cp.async.wait_group 1;" ::: "memory");
}
__device__ __forceinline__ void cp_wait0() {
    asm volatile("cp.async.wait_group 0;" ::: "memory");
}
__device__ __forceinline__ void ldsm4(uint32_t (&r)[4], uint32_t addr) {
    asm volatile("ldmatrix.sync.aligned.m8n8.x4.shared.b16 {%0,%1,%2,%3}, [%4];"
                 : "=r"(r[0]), "=r"(r[1]), "=r"(r[2]), "=r"(r[3]) : "r"(addr));
}
__device__ __forceinline__ void ldsm4t(uint32_t (&r)[4], uint32_t addr) {
    asm volatile("ldmatrix.sync.aligned.m8n8.x4.trans.shared.b16 {%0,%1,%2,%3}, [%4];"
                 : "=r"(r[0]), "=r"(r[1]), "=r"(r[2]), "=r"(r[3]) : "r"(addr));
}
__device__ __forceinline__ void mma16816(float (&c)[4], const uint32_t (&a)[4],
                                         uint32_t b0, uint32_t b1) {
    asm volatile(
        "mma.sync.aligned.m16n8k16.row.col.f32.f16.f16.f32 "
        "{%0,%1,%2,%3}, {%4,%5,%6,%7}, {%8,%9}, {%0,%1,%2,%3};"
        : "+f"(c[0]), "+f"(c[1]), "+f"(c[2]), "+f"(c[3])
        : "r"(a[0]), "r"(a[1]), "r"(a[2]), "r"(a[3]), "r"(b0), "r"(b1));
}
__device__ __forceinline__ uint32_t pack_h2(float a, float b) {
    __half2 h = __floats2half2_rn(a, b);
    return *(uint32_t*)&h;
}

// ---------------- pre-pass: Winograd weight transform ----------------

__global__ void wgconv_kernel(const float* __restrict__ W) {
    int idx = blockIdx.x * 256 + threadIdx.x;   // 65536 = (c,f)
    float g0 = W[idx];
    float g1 = W[65536 + idx];
    float g2 = W[131072 + idx];
    g_wt[idx]              = __float2half_rn(g0);
    g_wt[65536 + idx]      = __float2half_rn(0.5f * (g0 + g1 + g2));
    g_wt[131072 + idx]     = __float2half_rn(0.5f * (g0 - g1 + g2));
    g_wt[196608 + idx]     = __float2half_rn(g2);
}

// ---------------- main kernel ----------------

__global__ __launch_bounds__(NTHREADS, 1)
void conv1d_wino_kernel(const float* __restrict__ x,
                        const float* __restrict__ bias,
                        float* __restrict__ out)
{
    extern __shared__ __align__(128) uint8_t smem[];
    const uint32_t sm = smem_u32(smem);

    const int tid  = threadIdx.x;
    const int wid  = tid >> 5;
    const int lane = tid & 31;

    const int f0  = blockIdx.x * 128;       // feature tile
    const int t0  = blockIdx.y * 64;        // tile-pair block
    const int img = blockIdx.z;

    const float* xb = x   + (size_t)img * (1024 * 256);
    float*       ob = out + (size_t)img * (1022 * 256);

    // warps 0-3: phases 0,1; warps 4-7: phases 2,3; 2x2 spatial grid each
    const int phb = (wid >> 2) * 2;
    const int wq  = wid & 3;
    const int wm  = (wq >> 1) * 32;          // tile rows within 64
    const int wn  = (wq & 1) * 64;           // feats within 128

    const uint32_t a_lane = (uint32_t)(wm + (lane & 15)) * Z_STRIDE + (lane >> 4) * 16;
    const uint32_t b_lane = (uint32_t)(lane & 15) * B_STRIDE
                          + (uint32_t)(wn + (lane >> 4) * 8) * 2;

    // ---- staging: chunk s = channels [s*32, s*32+32) ----
    auto stage = [&](int s) {
        const uint32_t slot = sm + (s % 3) * SLOT;
        // x fp32: 130 half-rows... rows 0..129, 2 segs of 16 fp32
        #pragma unroll
        for (int h = tid; h < 260; h += NTHREADS) {
            const int row = h >> 1, seg = h & 1;
            int grow = 2 * t0 + row;
            if (grow > 1023) grow = 1023;
            const float* src = xb + (size_t)grow * 256 + s * 32 + seg * 16;
            const uint32_t d = slot + (uint32_t)row * X_STRIDE + seg * 64;
            cp16(d,      src);
            cp16(d + 16, src + 4);
            cp16(d + 32, src + 8);
            cp16(d + 48, src + 12);
        }
        // B: 4 phases x 32 k-rows x 128 feats fp16
        {
            const int row = tid >> 1, half = tid & 1;   // 128 rows x 2 halves
            const int ph = row >> 5, kr = row & 31;
            const __half* src = g_wt + (size_t)ph * 65536 + (size_t)(s * 32 + kr) * 256
                              + f0 + half * 64;
            const uint32_t d = slot + SLOT_X + ph * B_PHASE
                             + (uint32_t)kr * B_STRIDE + half * 128;
            #pragma unroll
            for (int q = 0; q < 8; ++q) cp16(d + q * 16, src + q * 8);
        }
        cp_commit();
    };

    // ---- transform: x fp32 slot -> z fp16 (4 phases), buf = s&1 ----
    auto transform = [&](int s) {
        const float* xs = (const float*)(smem + (s % 3) * SLOT);
        const int ti = tid >> 2;
        const int cg = (tid & 3) * 8;
        float4 d[4][2];
        #pragma unroll
        for (int k = 0; k < 4; ++k) {
            const float* r = xs + (size_t)(2 * ti + k) * 36 + cg;  // 36 fp32 = 144B
            d[k][0] = *(const float4*)(r);
            d[k][1] = *(const float4*)(r + 4);
        }
        uint8_t* zb = smem + OFF_Z + (s & 1) * Z_BUF + ti * Z_STRIDE + cg * 2;
        #pragma unroll
        for (int half = 0; half < 2; ++half) {
            const float* d0 = (const float*)&d[0][half];
            const float* d1 = (const float*)&d[1][half];
            const float* d2 = (const float*)&d[2][half];
            const float* d3 = (const float*)&d[3][half];
            uint2 z0, z1, z2, z3;
            z0.x = pack_h2(d0[0] - d2[0], d0[1] - d2[1]);
            z0.y = pack_h2(d0[2] - d2[2], d0[3] - d2[3]);
            z1.x = pack_h2(d1[0] + d2[0], d1[1] + d2[1]);
            z1.y = pack_h2(d1[2] + d2[2], d1[3] + d2[3]);
            z2.x = pack_h2(d2[0] - d1[0], d2[1] - d1[1]);
            z2.y = pack_h2(d2[2] - d1[2], d2[3] - d1[3]);
            z3.x = pack_h2(d1[0] - d3[0], d1[1] - d3[1]);
            z3.y = pack_h2(d1[2] - d3[2], d1[3] - d3[3]);
            *(uint2*)(zb + 0 * Z_PHASE + half * 8) = z0;
            *(uint2*)(zb + 1 * Z_PHASE + half * 8) = z1;
            *(uint2*)(zb + 2 * Z_PHASE + half * 8) = z2;
            *(uint2*)(zb + 3 * Z_PHASE + half * 8) = z3;
        }
    };

    // accumulators: [phase-pair][mt][nt][4]
    float acc[2][2][8][4];
    #pragma unroll
    for (int pp = 0; pp < 2; ++pp)
        #pragma unroll
        for (int mt = 0; mt < 2; ++mt)
            #pragma unroll
            for (int nt = 0; nt < 8; ++nt)
                #pragma unroll
                for (int q = 0; q < 4; ++q)
                    acc[pp][mt][nt][q] = 0.f;

    // ---- prologue ----
    stage(0);
    stage(1);
    cp_wait1();
    __syncthreads();
    transform(0);
    __syncthreads();

    for (int t = 0; t < NCHUNK; ++t) {
        if (t + 2 < NCHUNK) stage(t + 2);

        // MMA block on zA buf (t&1), B slot (t%3)
        const uint32_t Ab = sm + OFF_Z + (t & 1) * Z_BUF;
        const uint32_t Bb = sm + (t % 3) * SLOT + SLOT_X;
        #pragma unroll
        for (int pp = 0; pp < 2; ++pp) {
            const int p = phb + pp;
            const uint32_t Ap = Ab + p * Z_PHASE;
            const uint32_t Bp = Bb + p * B_PHASE;
            #pragma unroll
            for (int ks = 0; ks < 2; ++ks) {
                uint32_t af[2][4];
                ldsm4(af[0], Ap + a_lane + ks * 32);
                ldsm4(af[1], Ap + a_lane + 16 * Z_STRIDE + ks * 32);
                uint32_t bf[4][4];
                #pragma unroll
                for (int n2 = 0; n2 < 4; ++n2)
                    ldsm4t(bf[n2], Bp + b_lane + ks * (16 * B_STRIDE) + n2 * 32);
                #pragma unroll
                for (int mt = 0; mt < 2; ++mt)
                    #pragma unroll
                    for (int n2 = 0; n2 < 4; ++n2) {
                        mma16816(acc[pp][mt][2 * n2],     af[mt], bf[n2][0], bf[n2][1]);
                        mma16816(acc[pp][mt][2 * n2 + 1], af[mt], bf[n2][2], bf[n2][3]);
                    }
            }
        }

        if (t + 2 < NCHUNK)      cp_wait1();
        else if (t + 1 < NCHUNK) cp_wait0();
        __syncthreads();
        if (t + 1 < NCHUNK) transform(t + 1);
        __syncthreads();
    }

    // ---- epilogue: warps 4-7 ship m2,m3 via smem; warps 0-3 combine+store ----
    if (wid >= 4) {
        uint8_t* ex = smem + (size_t)(wid - 4) * 16384;
        #pragma unroll
        for (int pp = 0; pp < 2; ++pp)
            #pragma unroll
            for (int mt = 0; mt < 2; ++mt)
                #pragma unroll
                for (int nt = 0; nt < 8; ++nt)
                    *(float4*)(ex + (((pp * 2 + mt) * 8 + nt) * 512) + lane * 16)
                        = *(const float4*)&acc[pp][mt][nt][0];
    }
    __syncthreads();

    if (wid < 4) {
        const uint8_t* ex = smem + (size_t)wq * 16384;
        const int g  = lane >> 2;
        const int tq = lane & 3;
        #pragma unroll
        for (int nt = 0; nt < 8; ++nt) {
            const int col = f0 + wn + nt * 8 + tq * 2;
            const float b0 = __ldg(bias + col);
            const float b1 = __ldg(bias + col + 1);
            #pragma unroll
            for (int mt = 0; mt < 2; ++mt) {
                float4 m2 = *(const float4*)(ex + (((0 * 2 + mt) * 8 + nt) * 512) + lane * 16);
                float4 m3 = *(const float4*)(ex + (((1 * 2 + mt) * 8 + nt) * 512) + lane * 16);
                const float* m0 = acc[0][mt][nt];
                const float* m1 = acc[1][mt][nt];
                const int r = t0 + wm + mt * 16 + g;      // tile-pair index
                if (r < NTILES) {
                    float y00 = m0[0] + m1[0] + m2.x + b0;
                    float y01 = m0[1] + m1[1] + m2.y + b1;
                    float y10 = m1[0] - m2.x - m3.x + b0;
                    float y11 = m1[1] - m2.y - m3.y + b1;
                    *(float2*)(ob + (size_t)(2 * r) * 256 + col)     = make_float2(y00, y01);
                    *(float2*)(ob + (size_t)(2 * r + 1) * 256 + col) = make_float2(y10, y11);
                }
                const int r2 = r + 8;
                if (r2 < NTILES) {
                    float y00 = m0[2] + m1[2] + m2.z + b0;
                    float y01 = m0[3] + m1[3] + m2.w + b1;
                    float y10 = m1[2] - m2.z - m3.z + b0;
                    float y11 = m1[3] - m2.w - m3.w + b1;
                    *(float2*)(ob + (size_t)(2 * r2) * 256 + col)     = make_float2(y00, y01);
                    *(float2*)(ob + (size_t)(2 * r2 + 1) * 256 + col) = make_float2(y10, y11);
                }
            }
        }
    }
}

}  // namespace

extern "C" void kernel_launch(void* const* d_in, const int* in_sizes, int n_in,
                              void* d_out, int out_size)
{
    const float* x  = (const float*)d_in[0];   // [8,32,1024,256]
    const float* w  = (const float*)d_in[1];   // [3,256,256]
    const float* b  = (const float*)d_in[2];   // [256]
    float* out      = (float*)d_out;           // [8,32,1022,256]

    wgconv_kernel<<<256, 256>>>(w);            // Winograd weight transform

    cudaFuncSetAttribute(conv1d_wino_kernel,
                         cudaFuncAttributeMaxDynamicSharedMemorySize, SMEM_TOTAL);

    dim3 grid(2, 8, 256);                      // f-tiles, tile-blocks, images
    conv1d_wino_kernel<<<grid, NTHREADS, SMEM_TOTAL>>>(x, b, out);
}